// round 3
// baseline (speedup 1.0000x reference)
#include <cuda_runtime.h>
#include <cstdint>

#define BATCH   2048
#define TT      50
#define NNODES  23
#define FF      4
#define HH      64
#define FUT     10
#define BPC     4                 // batches per CTA
#define ROWS    (BPC*NNODES)      // 92
#define THREADS 512
#define RS      68                // padded row stride (floats); 68*4=272B = 17*16B (16B aligned, conflict-free for .128)

#define SMEM_FLOATS (12288+12288+3*ROWS*RS+BPC*NNODES*24+BPC*NNODES*FF+256+64+192+192+2048+32+128+4)

typedef unsigned long long u64;

// packed fp32x2 FMA: d.lo += a.lo*b.lo ; d.hi += a.hi*b.hi  (full-rate fma pipe on sm_103a)
__device__ __forceinline__ void fma2(u64& d, u64 a, u64 b) {
    asm("fma.rn.f32x2 %0, %1, %2, %0;" : "+l"(d) : "l"(a), "l"(b));
}
__device__ __forceinline__ float2 unpk(u64 v) {
    float2 r; asm("mov.b64 {%0, %1}, %2;" : "=f"(r.x), "=f"(r.y) : "l"(v)); return r;
}
__device__ __forceinline__ u64 dup2(float a) {
    u64 r; asm("mov.b64 %0, {%1, %1};" : "=l"(r) : "f"(a)); return r;
}

__device__ __forceinline__ float sigmoidf_(float x) {
    return __fdividef(1.f, 1.f + __expf(-x));
}
__device__ __forceinline__ float tanhf_(float x) {
    return __fdividef(2.f, 1.f + __expf(-2.f * x)) - 1.f;
}

extern "C" __global__ void __launch_bounds__(THREADS, 1)
gwm_kernel(const float* __restrict__ x_seq, const float* __restrict__ adj_seq,
           const float* __restrict__ W_gcn, const float* __restrict__ b_gcn,
           const float* __restrict__ W_ih,  const float* __restrict__ W_hh,
           const float* __restrict__ b_ih,  const float* __restrict__ b_hh,
           const float* __restrict__ W_d1,  const float* __restrict__ b_d1,
           const float* __restrict__ W_d2,  const float* __restrict__ b_d2,
           float* __restrict__ out)
{
    extern __shared__ float sm[];
    float* sWI  = sm;                       // [g3*64+j][64]
    float* sWH  = sWI + 12288;
    float* sSup = sWH + 12288;              // support; reused as z-scratch in phase 3; d1 in decode
    float* sSpa = sSup + ROWS*RS;
    float* sH   = sSpa + ROWS*RS;
    float* sAdj = sH   + ROWS*RS;           // [r][24]
    float* sX   = sAdj + BPC*NNODES*24;     // [r][4]
    float* sWg  = sX   + BPC*NNODES*FF;     // [j][4]
    float* sbg  = sWg  + 256;
    float* sbi  = sbg  + 64;
    float* sbh  = sbi  + 192;
    float* sWd1 = sbh  + 192;               // [q][64]
    float* sbd1 = sWd1 + 2048;
    float* sWd2 = sbd1 + 32;                // [f][32]
    float* sbd2 = sWd2 + 128;

    const int tid  = threadIdx.x;
    const int w    = tid >> 5;
    const int lane = tid & 31;
    const int b0   = blockIdx.x * BPC;

    // ---- load all weights once ----
    for (int e = tid; e < 12288; e += THREADS) sWI[e] = W_ih[e];
    for (int e = tid; e < 12288; e += THREADS) sWH[e] = W_hh[e];
    for (int e = tid; e < 256;   e += THREADS) sWg[e] = W_gcn[e];
    for (int e = tid; e < 2048;  e += THREADS) sWd1[e] = W_d1[e];
    if (tid < 64)  sbg[tid] = b_gcn[tid];
    if (tid < 192) sbi[tid] = b_ih[tid];
    if (tid >= 192 && tid < 384) sbh[tid-192] = b_hh[tid-192];
    if (tid < 32)  sbd1[tid] = b_d1[tid];
    if (tid < 128) sWd2[tid] = W_d2[tid];
    if (tid < 4)   sbd2[tid] = b_d2[tid];
    for (int e = tid; e < ROWS*RS; e += THREADS) sH[e] = 0.f;
    __syncthreads();

    // phase-3 row mapping: lane -> rows lane, lane+32, lane+64
    const int j0 = w * 4;
    int  rr_[3]; bool val_[3];
#pragma unroll
    for (int rg = 0; rg < 3; ++rg) {
        int r = rg*32 + lane;
        val_[rg] = (r < ROWS);
        rr_[rg]  = val_[rg] ? r : 0;
    }

    for (int t = 0; t < TT + FUT; ++t) {
        const bool hist = (t < TT);
        if (hist) {
            for (int e = tid; e < BPC*NNODES*NNODES; e += THREADS) {
                int bl = e / (NNODES*NNODES);
                int i  = e - bl*(NNODES*NNODES);
                int n  = i / NNODES, m = i - n*NNODES;
                sAdj[(bl*NNODES + n)*24 + m] =
                    adj_seq[((size_t)(b0+bl)*TT + t)*(NNODES*NNODES) + i];
            }
            for (int e = tid; e < BPC*NNODES*FF; e += THREADS) {
                int bl = e / (NNODES*FF);
                int i  = e - bl*(NNODES*FF);
                sX[e] = x_seq[((size_t)(b0+bl)*TT + t)*(NNODES*FF) + i];
            }
            __syncthreads();
        }

        // ---- phase 1: support = x @ Wg^T + bg ----
        for (int e = tid; e < ROWS*HH; e += THREADS) {
            int r = e >> 6, j = e & 63;
            const float* xp = sX + r*FF;
            float v = sbg[j];
            v = fmaf(xp[0], sWg[j*4+0], v);
            v = fmaf(xp[1], sWg[j*4+1], v);
            v = fmaf(xp[2], sWg[j*4+2], v);
            v = fmaf(xp[3], sWg[j*4+3], v);
            sSup[r*RS + j] = v;
        }
        __syncthreads();

        // ---- phase 2: spatial = relu(adj @ support), packed ----
        {
            const int rh = lane >> 4, jq = lane & 15;
            for (int p = w; p < 46; p += 16) {
                int r = 2*p + rh;
                int bl = r / NNODES;
                const float* arow = sAdj + r*24;
                const float* supb = sSup + (bl*NNODES)*RS;
                u64 a0 = 0ull, a1 = 0ull;
#pragma unroll
                for (int m = 0; m < NNODES; ++m) {
                    u64 am = dup2(arow[m]);
                    ulonglong2 s = *(const ulonglong2*)(supb + m*RS + 4*jq);
                    fma2(a0, am, s.x);
                    fma2(a1, am, s.y);
                }
                float2 f0 = unpk(a0), f1 = unpk(a1);
                float4 o;
                o.x = fmaxf(f0.x, 0.f); o.y = fmaxf(f0.y, 0.f);
                o.z = fmaxf(f1.x, 0.f); o.w = fmaxf(f1.y, 0.f);
                *(float4*)(sSpa + r*RS + 4*jq) = o;
            }
        }
        __syncthreads();

        // ---- phase 3 pass A: gates r,z (merged input+hidden accumulators) ----
        float rv[3][4];
        {
            u64 aR[3][4], aZ[3][4];
#pragma unroll
            for (int rg = 0; rg < 3; ++rg)
#pragma unroll
                for (int jj = 0; jj < 4; ++jj) { aR[rg][jj] = 0ull; aZ[rg][jj] = 0ull; }

            for (int kq = 0; kq < 16; ++kq) {
                ulonglong2 sv[3], hv[3];
#pragma unroll
                for (int rg = 0; rg < 3; ++rg) {
                    sv[rg] = *(const ulonglong2*)(sSpa + rr_[rg]*RS + kq*4);
                    hv[rg] = *(const ulonglong2*)(sH   + rr_[rg]*RS + kq*4);
                }
#pragma unroll
                for (int jj = 0; jj < 4; ++jj) {
                    const int jr = j0 + jj;
                    ulonglong2 wiR = *(const ulonglong2*)(sWI + jr*64        + kq*4);
                    ulonglong2 whR = *(const ulonglong2*)(sWH + jr*64        + kq*4);
                    ulonglong2 wiZ = *(const ulonglong2*)(sWI + (64+jr)*64   + kq*4);
                    ulonglong2 whZ = *(const ulonglong2*)(sWH + (64+jr)*64   + kq*4);
#pragma unroll
                    for (int rg = 0; rg < 3; ++rg) {
                        fma2(aR[rg][jj], sv[rg].x, wiR.x); fma2(aR[rg][jj], sv[rg].y, wiR.y);
                        fma2(aR[rg][jj], hv[rg].x, whR.x); fma2(aR[rg][jj], hv[rg].y, whR.y);
                        fma2(aZ[rg][jj], sv[rg].x, wiZ.x); fma2(aZ[rg][jj], sv[rg].y, wiZ.y);
                        fma2(aZ[rg][jj], hv[rg].x, whZ.x); fma2(aZ[rg][jj], hv[rg].y, whZ.y);
                    }
                }
            }
#pragma unroll
            for (int rg = 0; rg < 3; ++rg)
#pragma unroll
                for (int jj = 0; jj < 4; ++jj) {
                    const int j = j0 + jj;
                    float2 pr = unpk(aR[rg][jj]);
                    float2 pz = unpk(aZ[rg][jj]);
                    rv[rg][jj] = sigmoidf_(pr.x + pr.y + sbi[j] + sbh[j]);
                    float z    = sigmoidf_(pz.x + pz.y + sbi[64+j] + sbh[64+j]);
                    if (val_[rg]) sSup[rr_[rg]*RS + j] = z;   // park z (own thread reads it back)
                }
        }

        // ---- phase 3 pass B: gate n + h update ----
        float hnew[3][4];
        {
            u64 aNI[3][4], aNH[3][4];
#pragma unroll
            for (int rg = 0; rg < 3; ++rg)
#pragma unroll
                for (int jj = 0; jj < 4; ++jj) { aNI[rg][jj] = 0ull; aNH[rg][jj] = 0ull; }

            for (int kq = 0; kq < 16; ++kq) {
                ulonglong2 sv[3], hv[3];
#pragma unroll
                for (int rg = 0; rg < 3; ++rg) {
                    sv[rg] = *(const ulonglong2*)(sSpa + rr_[rg]*RS + kq*4);
                    hv[rg] = *(const ulonglong2*)(sH   + rr_[rg]*RS + kq*4);
                }
#pragma unroll
                for (int jj = 0; jj < 4; ++jj) {
                    const int jr = j0 + jj;
                    ulonglong2 wiN = *(const ulonglong2*)(sWI + (128+jr)*64 + kq*4);
                    ulonglong2 whN = *(const ulonglong2*)(sWH + (128+jr)*64 + kq*4);
#pragma unroll
                    for (int rg = 0; rg < 3; ++rg) {
                        fma2(aNI[rg][jj], sv[rg].x, wiN.x); fma2(aNI[rg][jj], sv[rg].y, wiN.y);
                        fma2(aNH[rg][jj], hv[rg].x, whN.x); fma2(aNH[rg][jj], hv[rg].y, whN.y);
                    }
                }
            }
#pragma unroll
            for (int rg = 0; rg < 3; ++rg)
#pragma unroll
                for (int jj = 0; jj < 4; ++jj) {
                    const int j = j0 + jj;
                    float2 pi = unpk(aNI[rg][jj]);
                    float2 ph = unpk(aNH[rg][jj]);
                    float nn = tanhf_(pi.x + pi.y + sbi[128+j] +
                                      rv[rg][jj] * (ph.x + ph.y + sbh[128+j]));
                    float z    = val_[rg] ? sSup[rr_[rg]*RS + j] : 0.f;
                    float hold = sH[rr_[rg]*RS + j];
                    hnew[rg][jj] = (1.f - z)*nn + z*hold;
                }
        }
        __syncthreads();   // all reads of sH / sSpa complete
#pragma unroll
        for (int rg = 0; rg < 3; ++rg)
            if (val_[rg]) {
#pragma unroll
                for (int jj = 0; jj < 4; ++jj) sH[rr_[rg]*RS + j0 + jj] = hnew[rg][jj];
            }
        __syncthreads();

        // ---- decode (future steps only) ----
        if (!hist) {
            const int s = t - TT;
            if (w < 8) {
                const int q0 = w * 4;
#pragma unroll
                for (int rg = 0; rg < 3; ++rg) {
                    int r  = rg*32 + lane;
                    int rr = (r < ROWS) ? r : 0;
                    const float4* hp = (const float4*)(sH + rr*RS);
                    float acc[4] = {0.f,0.f,0.f,0.f};
#pragma unroll 4
                    for (int kq = 0; kq < 16; ++kq) {
                        float4 hh = hp[kq];
#pragma unroll
                        for (int jj = 0; jj < 4; ++jj) {
                            const float4 wd = *(const float4*)(sWd1 + (q0+jj)*64 + kq*4);
                            float a = acc[jj];
                            a = fmaf(hh.x, wd.x, a); a = fmaf(hh.y, wd.y, a);
                            a = fmaf(hh.z, wd.z, a); a = fmaf(hh.w, wd.w, a);
                            acc[jj] = a;
                        }
                    }
                    if (r < ROWS) {
#pragma unroll
                        for (int jj = 0; jj < 4; ++jj)
                            sSup[r*RS + q0 + jj] = fmaxf(acc[jj] + sbd1[q0+jj], 0.f);
                    }
                }
            }
            __syncthreads();
            for (int e = tid; e < ROWS*FF; e += THREADS) {
                int r = e >> 2, f = e & 3;
                float v = sbd2[f];
#pragma unroll
                for (int q = 0; q < 32; ++q)
                    v = fmaf(sSup[r*RS + q], sWd2[f*32 + q], v);
                sX[e] = v;
                int bl = r / NNODES, n = r - bl*NNODES;
                out[(((size_t)(b0+bl)*FUT + s)*NNODES + n)*FF + f] = v;
            }
            __syncthreads();
        }
    }
}

extern "C" void kernel_launch(void* const* d_in, const int* in_sizes, int n_in,
                              void* d_out, int out_size) {
    const float* x_seq  = (const float*)d_in[0];
    const float* adj    = (const float*)d_in[1];
    const float* W_gcn  = (const float*)d_in[2];
    const float* b_gcn  = (const float*)d_in[3];
    const float* W_ih   = (const float*)d_in[4];
    const float* W_hh   = (const float*)d_in[5];
    const float* b_ih   = (const float*)d_in[6];
    const float* b_hh   = (const float*)d_in[7];
    const float* W_d1   = (const float*)d_in[8];
    const float* b_d1   = (const float*)d_in[9];
    const float* W_d2   = (const float*)d_in[10];
    const float* b_d2   = (const float*)d_in[11];
    float* out = (float*)d_out;

    const int smem_bytes = SMEM_FLOATS * (int)sizeof(float);
    cudaFuncSetAttribute(gwm_kernel, cudaFuncAttributeMaxDynamicSharedMemorySize, smem_bytes);
    gwm_kernel<<<BATCH / BPC, THREADS, smem_bytes>>>(
        x_seq, adj, W_gcn, b_gcn, W_ih, W_hh, b_ih, b_hh,
        W_d1, b_d1, W_d2, b_d2, out);
}

// round 6
// speedup vs baseline: 1.7944x; 1.7944x over previous
#include <cuda_runtime.h>
#include <cstdint>

#define BATCH   2048
#define TT      50
#define NNODES  23
#define FF      4
#define HH      64
#define FUT     10
#define BPC     2                 // batches per CTA
#define ROWS    (BPC*NNODES)      // 46
#define MPAD    48
#define THREADS 512
#define CS      132               // sC row stride (floats), 128 cols + pad
#define WS      192               // sWt row stride (floats)
#define SS      68                // sSup row stride

// smem floats: sWt 24576 | sC 6336 | sSup 3264 | sAdj 1104 | sX 184 | sWg 256
//              sbg 64 | sbrz 128 | sbin 64 | sbhn 64 | sWd1 2048 | sbd1 32 | sWd2 128 | sbd2 4
#define SMEM_FLOATS (24576+6336+3264+1104+184+256+64+128+64+64+2048+32+128+4)

typedef unsigned long long u64;

__device__ __forceinline__ void fma2(u64& d, u64 a, u64 b) {
    asm("fma.rn.f32x2 %0, %1, %2, %0;" : "+l"(d) : "l"(a), "l"(b));
}
__device__ __forceinline__ float2 unpk(u64 v) {
    float2 r; asm("mov.b64 {%0, %1}, %2;" : "=f"(r.x), "=f"(r.y) : "l"(v)); return r;
}
__device__ __forceinline__ u64 dup2(float a) {
    u64 r; asm("mov.b64 %0, {%1, %1};" : "=l"(r) : "f"(a)); return r;
}
__device__ __forceinline__ float sigmoidf_(float x) {
    return __fdividef(1.f, 1.f + __expf(-x));
}
__device__ __forceinline__ float tanhf_(float x) {
    return __fdividef(2.f, 1.f + __expf(-2.f * x)) - 1.f;
}

// one K-half (64 k) of the gate GEMM for this thread's 3x(2j x 3gate) tile
__device__ __forceinline__ void gemm_half(const float* __restrict__ sC,
                                          const float* __restrict__ sWt,
                                          int m0, int jr, int kb0,
                                          u64 acc[3][3]) {
#pragma unroll 2
    for (int kb = kb0; kb < kb0 + 16; ++kb) {
        float4 a0 = *(const float4*)(sC + (m0+0)*CS + kb*4);
        float4 a1 = *(const float4*)(sC + (m0+1)*CS + kb*4);
        float4 a2 = *(const float4*)(sC + (m0+2)*CS + kb*4);
#pragma unroll
        for (int kk = 0; kk < 4; ++kk) {
            const float* wr = sWt + (kb*4 + kk)*WS + jr;
            u64 br = *(const u64*)(wr);
            u64 bz = *(const u64*)(wr + 64);
            u64 bn = *(const u64*)(wr + 128);
            float f0 = kk==0 ? a0.x : kk==1 ? a0.y : kk==2 ? a0.z : a0.w;
            float f1 = kk==0 ? a1.x : kk==1 ? a1.y : kk==2 ? a1.z : a1.w;
            float f2 = kk==0 ? a2.x : kk==1 ? a2.y : kk==2 ? a2.z : a2.w;
            u64 d0 = dup2(f0), d1 = dup2(f1), d2 = dup2(f2);
            fma2(acc[0][0], d0, br); fma2(acc[0][1], d0, bz); fma2(acc[0][2], d0, bn);
            fma2(acc[1][0], d1, br); fma2(acc[1][1], d1, bz); fma2(acc[1][2], d1, bn);
            fma2(acc[2][0], d2, br); fma2(acc[2][1], d2, bz); fma2(acc[2][2], d2, bn);
        }
    }
}

extern "C" __global__ void __launch_bounds__(THREADS, 1)
gwm_kernel(const float* __restrict__ x_seq, const float* __restrict__ adj_seq,
           const float* __restrict__ W_gcn, const float* __restrict__ b_gcn,
           const float* __restrict__ W_ih,  const float* __restrict__ W_hh,
           const float* __restrict__ b_ih,  const float* __restrict__ b_hh,
           const float* __restrict__ W_d1,  const float* __restrict__ b_d1,
           const float* __restrict__ W_d2,  const float* __restrict__ b_d2,
           float* __restrict__ out)
{
    extern __shared__ float sm[];
    float* sWt  = sm;                 // [k=0..127][j=0..191]  k<64: W_ih^T, k>=64: W_hh^T
    float* sC   = sWt  + 24576;       // [48][132] : cols 0..63 spa, 64..127 h
    float* sSup = sC   + 6336;        // [48][68]
    float* sAdj = sSup + 3264;        // [r][24]
    float* sX   = sAdj + 1104;        // [r][4]
    float* sWg  = sX   + 184;         // [j][4]
    float* sbg  = sWg  + 256;
    float* sbrz = sbg  + 64;          // b_ih+b_hh for j 0..127 (r,z)
    float* sbin = sbrz + 128;         // b_ih[128+j]
    float* sbhn = sbin + 64;          // b_hh[128+j]
    float* sWd1 = sbhn + 64;          // [q][64]
    float* sbd1 = sWd1 + 2048;
    float* sWd2 = sbd1 + 32;          // [f][32]
    float* sbd2 = sWd2 + 128;

    const int tid  = threadIdx.x;
    const int w    = tid >> 5;
    const int lane = tid & 31;
    const int b0   = blockIdx.x * BPC;

    // GEMM tile mapping
    const int wm = w >> 3;            // 0..1
    const int wn = w & 7;             // 0..7
    const int ml = lane & 7;          // 0..7
    const int ng = lane >> 3;         // 0..3
    const int m0 = wm*24 + ml*3;      // rows m0..m0+2
    const int jr = wn*8 + ng*2;       // j (per gate), even, 0..62

    // ---- one-time setup ----
    for (int e = tid; e < 192*64; e += THREADS) {
        int j = e >> 6, k = e & 63;
        sWt[k*WS + j]        = W_ih[j*64 + k];
        sWt[(64+k)*WS + j]   = W_hh[j*64 + k];
    }
    for (int e = tid; e < 256;  e += THREADS) sWg[e]  = W_gcn[e];
    for (int e = tid; e < 2048; e += THREADS) sWd1[e] = W_d1[e];
    if (tid < 64)  sbg[tid]  = b_gcn[tid];
    if (tid < 128) sbrz[tid] = b_ih[tid] + b_hh[tid];
    if (tid >= 128 && tid < 192) sbin[tid-128] = b_ih[tid];
    if (tid >= 192 && tid < 256) sbhn[tid-192] = b_hh[tid-64];   // b_hh[128..191] (n gate)
    if (tid < 32)  sbd1[tid] = b_d1[tid];
    if (tid < 128) sWd2[tid] = W_d2[tid];
    if (tid < 4)   sbd2[tid] = b_d2[tid];
    for (int e = tid; e < MPAD*CS; e += THREADS) sC[e] = 0.f;   // spa=0, h0=0
    __syncthreads();

    for (int t = 0; t < TT + FUT; ++t) {
        const bool hist = (t < TT);
        if (hist) {
            for (int e = tid; e < BPC*NNODES*NNODES; e += THREADS) {
                int bl = e / (NNODES*NNODES);
                int i  = e - bl*(NNODES*NNODES);
                int n  = i / NNODES, m = i - n*NNODES;
                sAdj[(bl*NNODES + n)*24 + m] =
                    adj_seq[((size_t)(b0+bl)*TT + t)*(NNODES*NNODES) + i];
            }
            for (int e = tid; e < ROWS*FF; e += THREADS) {
                int bl = e / (NNODES*FF);
                int i  = e - bl*(NNODES*FF);
                sX[e] = x_seq[((size_t)(b0+bl)*TT + t)*(NNODES*FF) + i];
            }
            __syncthreads();
        }

        // ---- phase 1: support = x @ Wg^T + bg ----
        for (int e = tid; e < ROWS*HH; e += THREADS) {
            int r = e >> 6, j = e & 63;
            const float* xp = sX + r*FF;
            float v = sbg[j];
            v = fmaf(xp[0], sWg[j*4+0], v);
            v = fmaf(xp[1], sWg[j*4+1], v);
            v = fmaf(xp[2], sWg[j*4+2], v);
            v = fmaf(xp[3], sWg[j*4+3], v);
            sSup[r*SS + j] = v;
        }
        __syncthreads();

        // ---- phase 2: spa = relu(adj @ support) -> sC[:, 0..63] (row-major) ----
        {
            const int rh = lane >> 4, jq = lane & 15;
            for (int p = w; p < 23; p += 16) {
                int r  = 2*p + rh;                   // 0..45
                int bl = r / NNODES;
                const float* arow = sAdj + r*24;
                const float* supb = sSup + (bl*NNODES)*SS;
                u64 a0 = 0ull, a1 = 0ull;
#pragma unroll
                for (int m = 0; m < NNODES; ++m) {
                    u64 am = dup2(arow[m]);
                    ulonglong2 s = *(const ulonglong2*)(supb + m*SS + 4*jq);
                    fma2(a0, am, s.x);
                    fma2(a1, am, s.y);
                }
                float2 f0 = unpk(a0), f1 = unpk(a1);
                float4 o;
                o.x = fmaxf(f0.x, 0.f); o.y = fmaxf(f0.y, 0.f);
                o.z = fmaxf(f1.x, 0.f); o.w = fmaxf(f1.y, 0.f);
                *(float4*)(sC + r*CS + 4*jq) = o;
            }
        }
        __syncthreads();

        // ---- phase 3: gate GEMM (all 512 threads) ----
        u64 accLo[3][3], accHi[3][3];
#pragma unroll
        for (int mi = 0; mi < 3; ++mi)
#pragma unroll
            for (int g = 0; g < 3; ++g) { accLo[mi][g] = 0ull; accHi[mi][g] = 0ull; }

        gemm_half(sC, sWt, m0, jr, 0,  accLo);   // k 0..63  : spa @ W_ih^T
        gemm_half(sC, sWt, m0, jr, 16, accHi);   // k 64..127: h   @ W_hh^T

        // ---- GRU epilogue (in registers) ----
        float hnew[3][2];
        {
            const float2 brz_r = *(const float2*)(sbrz + jr);
            const float2 brz_z = *(const float2*)(sbrz + 64 + jr);
            const float2 bin_n = *(const float2*)(sbin + jr);
            const float2 bhn_n = *(const float2*)(sbhn + jr);
#pragma unroll
            for (int mi = 0; mi < 3; ++mi) {
                float2 rL = unpk(accLo[mi][0]), rH = unpk(accHi[mi][0]);
                float2 zL = unpk(accLo[mi][1]), zH = unpk(accHi[mi][1]);
                float2 nI = unpk(accLo[mi][2]), nH = unpk(accHi[mi][2]);
                float r0 = sigmoidf_(rL.x + rH.x + brz_r.x);
                float r1 = sigmoidf_(rL.y + rH.y + brz_r.y);
                float z0 = sigmoidf_(zL.x + zH.x + brz_z.x);
                float z1 = sigmoidf_(zL.y + zH.y + brz_z.y);
                float n0 = tanhf_(nI.x + bin_n.x + r0*(nH.x + bhn_n.x));
                float n1 = tanhf_(nI.y + bin_n.y + r1*(nH.y + bhn_n.y));
                float2 ho = *(const float2*)(sC + (m0+mi)*CS + 64 + jr);
                hnew[mi][0] = (1.f - z0)*n0 + z0*ho.x;
                hnew[mi][1] = (1.f - z1)*n1 + z1*ho.y;
            }
        }
        __syncthreads();    // all GEMM reads of sC done
#pragma unroll
        for (int mi = 0; mi < 3; ++mi)
            *(float2*)(sC + (m0+mi)*CS + 64 + jr) = make_float2(hnew[mi][0], hnew[mi][1]);
        __syncthreads();

        // ---- decode (future steps only) ----
        if (!hist) {
            const int s = t - TT;
            if (w < 8) {
                const int q0 = w * 4;
#pragma unroll
                for (int rg = 0; rg < 2; ++rg) {
                    int r  = rg*32 + lane;
                    int rr = (r < ROWS) ? r : 0;
                    const float* hp = sC + rr*CS + 64;
                    float acc[4] = {0.f,0.f,0.f,0.f};
#pragma unroll 4
                    for (int kq = 0; kq < 16; ++kq) {
                        float4 hh = *(const float4*)(hp + kq*4);
#pragma unroll
                        for (int jj = 0; jj < 4; ++jj) {
                            const float4 wd = *(const float4*)(sWd1 + (q0+jj)*64 + kq*4);
                            float a = acc[jj];
                            a = fmaf(hh.x, wd.x, a); a = fmaf(hh.y, wd.y, a);
                            a = fmaf(hh.z, wd.z, a); a = fmaf(hh.w, wd.w, a);
                            acc[jj] = a;
                        }
                    }
                    if (r < ROWS) {
#pragma unroll
                        for (int jj = 0; jj < 4; ++jj)
                            sSup[r*SS + q0 + jj] = fmaxf(acc[jj] + sbd1[q0+jj], 0.f);
                    }
                }
            }
            __syncthreads();
            for (int e = tid; e < ROWS*FF; e += THREADS) {
                int r = e >> 2, f = e & 3;
                float v = sbd2[f];
#pragma unroll
                for (int q = 0; q < 32; ++q)
                    v = fmaf(sSup[r*SS + q], sWd2[f*32 + q], v);
                sX[e] = v;
                int bl = r / NNODES, n = r - bl*NNODES;
                out[(((size_t)(b0+bl)*FUT + s)*NNODES + n)*FF + f] = v;
            }
            __syncthreads();
        }
    }
}

extern "C" void kernel_launch(void* const* d_in, const int* in_sizes, int n_in,
                              void* d_out, int out_size) {
    const float* x_seq  = (const float*)d_in[0];
    const float* adj    = (const float*)d_in[1];
    const float* W_gcn  = (const float*)d_in[2];
    const float* b_gcn  = (const float*)d_in[3];
    const float* W_ih   = (const float*)d_in[4];
    const float* W_hh   = (const float*)d_in[5];
    const float* b_ih   = (const float*)d_in[6];
    const float* b_hh   = (const float*)d_in[7];
    const float* W_d1   = (const float*)d_in[8];
    const float* b_d1   = (const float*)d_in[9];
    const float* W_d2   = (const float*)d_in[10];
    const float* b_d2   = (const float*)d_in[11];
    float* out = (float*)d_out;

    const int smem_bytes = SMEM_FLOATS * (int)sizeof(float);
    cudaFuncSetAttribute(gwm_kernel, cudaFuncAttributeMaxDynamicSharedMemorySize, smem_bytes);
    gwm_kernel<<<BATCH / BPC, THREADS, smem_bytes>>>(
        x_seq, adj, W_gcn, b_gcn, W_ih, W_hh, b_ih, b_hh,
        W_d1, b_d1, W_d2, b_d2, out);
}